// round 17
// baseline (speedup 1.0000x reference)
#include <cuda_runtime.h>
#include <math.h>

// NarrowParabolicEq — time-parallel persistent kernel.
// R17: squaring tile TRANSPOSED to s[row][tap] -> conflict-free B loads
// (consecutive d -> consecutive banks), broadcast A loads. Math identical.
//  P0: T = S^10 band taps (radius 6) + y0                        [1 barrier]
//  Ladder L=0..6: banded squaring T^{2^{L+1}}, smem-tiled;        [7 barriers]
//     chain blocks fold start-product matvecs into the slack.
//  P9: 25 chains x ~8 T-applications, fully block-local.          [0 barriers]

#define NPTS 500
#define NTH  256
#define NBLK 125
#define NLVL 8
#define TAPW 129
#define NCH  25
#define MITV 8
#define YSLOTS 528
#define SMEM_BYTES (76 * 1024)
#define VOFF0 8448
#define VOFF1 8960

typedef unsigned long long u64;
union F2U { float2 f; u64 u; };

__device__ __forceinline__ u64 pk2(float lo, float hi) { F2U x; x.f.x = lo; x.f.y = hi; return x.u; }
__device__ __forceinline__ float lo2(u64 v) { F2U a; a.u = v; return a.f.x; }
__device__ __forceinline__ float hi2(u64 v) { F2U a; a.u = v; return a.f.y; }

__device__ __forceinline__ u64 fma2(u64 a, u64 b, u64 c)
{ u64 d; asm("fma.rn.f32x2 %0,%1,%2,%3;" : "=l"(d) : "l"(a), "l"(b), "l"(c)); return d; }
__device__ __forceinline__ u64 add2(u64 a, u64 b)
{ u64 d; asm("add.rn.f32x2 %0,%1,%2;" : "=l"(d) : "l"(a), "l"(b)); return d; }
__device__ __forceinline__ u64 mul2(u64 a, u64 b)
{ u64 d; asm("mul.rn.f32x2 %0,%1,%2;" : "=l"(d) : "l"(a), "l"(b)); return d; }

__device__ float2 gOp[NLVL][TAPW][NPTS];
__device__ int gCnt;
__device__ volatile int gGen;

__constant__ int cRLV[NLVL] = {6, 9, 12, 16, 22, 30, 44, 64};

__device__ __forceinline__ void gsync(int& myg)
{
    __syncthreads();
    if (threadIdx.x == 0) {
        __threadfence();
        if (atomicAdd(&gCnt, 1) == NBLK - 1) {
            gCnt = 0;
            __threadfence();
            gGen = myg + 1;
        } else {
            while (gGen == myg) { }
        }
        myg++;
        __threadfence();
    }
    __syncthreads();
}

__device__ __forceinline__ void coeffs_at(int q, float refc, float refd,
                                          float* hcli, float* hch2)
{
    const float K0 = 0.209439510239f;
    if (q >= 1 && q <= NPTS - 2) {
        const float dx = 2000.0f / 499.0f;
        float cli = (1.0f / (dx * dx)) / (2.0f * K0);
        float z  = (2000.0f / 499.0f) * (float)q;
        float zz = 2.0f * (z - refd) / refd;
        float c  = refc * (1.0f + 0.00737f * (zz - 1.0f + expf(-zz)));
        float r  = 1500.0f / c;
        float het = r * r - 1.0f;
        float ch = K0 * het;
        *hcli = 0.1f * cli;
        *hch2 = 0.1f * (ch - 2.0f * cli);
    } else {
        *hcli = 0.0f; *hch2 = 0.0f;
    }
}

extern __shared__ float2 sbuf[];

__global__ __launch_bounds__(NTH, 1)
void pe_all(const float* __restrict__ params, float* __restrict__ out, int n_save)
{
    const int tid = threadIdx.x;
    const int b   = blockIdx.x;
    int myg = 0;
    if (tid == 0) myg = gGen;

    const float refc = params[0];
    const float refd = params[1];
    const int nitv = n_save - 1;
    const int n0 = MITV * b;
    const bool is_chain = (b < NCH) && (n0 <= nitv);

    float2* v0 = sbuf + VOFF0;
    float2* v1 = sbuf + VOFF1;

    // ================= P0: base taps (fp32) + chain y0 =================
    if (tid < 4) {
        int p = 4 * b + tid;
        if (p < NPTS) {
            float pcF[15], qcF[15];
            {
                float cD[7] = {1.f, 1.f, 0.5f, 1.f/6.f, 1.f/24.f, 1.f/120.f, 1.f/600.f};
                float R2[15], R4[15], R8[15], R10[15];
                for (int m = 0; m < 15; m++) {
                    float s = 0.f;
                    for (int j = 0; j <= 6; j++)
                        if (m - j >= 0 && m - j <= 6) s += cD[j] * cD[m - j];
                    R2[m] = s;
                }
                for (int m = 0; m < 15; m++) {
                    float s = 0.f;
                    for (int j = 0; j <= m; j++) s += R2[j] * R2[m - j];
                    R4[m] = s;
                }
                for (int m = 0; m < 15; m++) {
                    float s = 0.f;
                    for (int j = 0; j <= m; j++) s += R4[j] * R4[m - j];
                    R8[m] = s;
                }
                for (int m = 0; m < 15; m++) {
                    float s = 0.f;
                    for (int j = 0; j <= m; j++) s += R8[j] * R2[m - j];
                    R10[m] = s;
                }
                for (int m = 0; m < 15; m++) {
                    if ((m & 1) == 0) {
                        pcF[m] = ((m & 3) == 0) ? R10[m] : -R10[m];
                        qcF[m] = 0.f;
                    } else {
                        qcF[m] = ((m & 3) == 1) ? R10[m] : -R10[m];
                        pcF[m] = 0.f;
                    }
                }
            }
            float cliA[19], ch2A[19];
            #pragma unroll
            for (int j = 0; j < 19; j++)
                coeffs_at(p - 9 + j, refc, refd, &cliA[j], &ch2A[j]);
            float w[19], Pt[13], Qt[13];
            #pragma unroll
            for (int j = 0; j < 19; j++) w[j] = 0.f;
            w[9] = 1.f;
            #pragma unroll
            for (int j = 0; j < 13; j++) { Pt[j] = 0.f; Qt[j] = 0.f; }
            Pt[6] = pcF[0];
            #pragma unroll
            for (int k = 1; k <= 14; k++) {
                float nw[19];
                #pragma unroll
                for (int o = 0; o < 19; o++) {
                    float acc = w[o] * ch2A[o];
                    if (o > 0)  acc += w[o - 1] * cliA[o - 1];
                    if (o < 18) acc += w[o + 1] * cliA[o + 1];
                    nw[o] = acc;
                }
                #pragma unroll
                for (int o = 0; o < 19; o++) w[o] = nw[o];
                #pragma unroll
                for (int o2 = 0; o2 < 13; o2++) {
                    Pt[o2] += pcF[k] * w[o2 + 3];
                    Qt[o2] += qcF[k] * w[o2 + 3];
                }
            }
            #pragma unroll
            for (int j = 0; j < 13; j++)
                gOp[0][58 + j][p] = make_float2(Pt[j], Qt[j]);
        }
    }
    if (is_chain) {
        const float K0 = 0.209439510239f;
        const float SINE = 0.0261769483f;
        float ww  = sqrtf(2.0f * logf(2.0f)) / (K0 * SINE);
        float amp = 1.0f / (sqrtf(3.14159265358979f) * ww);
        for (int p = tid; p < NPTS; p += NTH) {
            float z = (2000.0f / 499.0f) * (float)p;
            float a = (z - 100.0f) / ww;
            v0[p] = make_float2(amp * expf(-a * a), 0.f);
        }
    }
    gsync(myg);

    // ============ Ladder (transposed tile) + chain-start products ============
    float2* src = v0;
    float2* dst = v1;
    for (int L = 0; L < NLVL - 1; L++) {
        const int Rin  = cRLV[L];
        const int Rout = cRLV[L + 1];
        const int Win   = 2 * Rin + 1;
        const int rowsIn = 4 + 2 * Rin;
        const int WinP   = Win + 1;             // transposed pitch (pad)
        const int r0 = 4 * b;

        // stage: s[lr][tap]; read order stays global-coalesced (lr fastest)
        for (int i = tid; i < Win * rowsIn; i += NTH) {
            int tap = i / rowsIn;
            int lr  = i - tap * rowsIn;
            int r   = r0 - Rin + lr;
            sbuf[lr * WinP + tap] =
                (r >= 0 && r < NPTS) ? gOp[L][64 - Rin + tap][r] : make_float2(0.f, 0.f);
        }
        __syncthreads();

        const int Wout = 2 * Rout + 1;
        for (int i = tid; i < 4 * Wout; i += NTH) {
            int row = i / Wout;
            int d   = i - row * Wout - Rout;
            int r   = r0 + row;
            if (r >= NPTS) continue;
            int olo = (-Rin > d - Rin) ? -Rin : d - Rin;
            int ohi = ( Rin < d + Rin) ?  Rin : d + Rin;
            float pp = 0.f, qq = 0.f;
            const float2* arow = sbuf + (Rin + row) * WinP + Rin;
            for (int o = olo; o <= ohi; o++) {
                float2 A = arow[o];                                  // broadcast
                float2 B = sbuf[(Rin + row + o) * WinP + (d - o + Rin)]; // conflict-free in d
                pp += A.x * B.x - A.y * B.y;
                qq += A.x * B.y + A.y * B.x;
            }
            gOp[L + 1][64 + d][r] = make_float2(pp, qq);
        }
        gsync(myg);

        if (is_chain && ((n0 >> (L + 1)) & 1)) {
            const int R = cRLV[L + 1];
            for (int p = tid; p < NPTS; p += NTH) {
                int olo = (p < R) ? -p : -R;
                int ohi = (NPTS - 1 - p < R) ? NPTS - 1 - p : R;
                float a1x = 0.f, a1y = 0.f, a2x = 0.f, a2y = 0.f;
                for (int o = olo; o <= ohi; o++) {
                    float2 PQ = gOp[L + 1][64 + o][p];
                    float2 v  = src[p + o];
                    a1x += PQ.x * v.x;  a1y += PQ.x * v.y;
                    a2x += PQ.y * v.x;  a2y += PQ.y * v.y;
                }
                dst[p] = make_float2(a1x - a2y, a1y + a2x);
            }
            __syncthreads();
            float2* tmp = src; src = dst; dst = tmp;
        }
    }

    // ================= P9: chains, fully local =================
    if (is_chain) {
        u64* YA = (u64*)sbuf;
        u64* YB = YA + YSLOTS;
        const int p0 = 2 * tid;
        const int half = n_save * NPTS;

        u64 Pa[13], Qa[13], Pb[13], Qb[13];
        #pragma unroll
        for (int j = 0; j < 13; j++) {
            float2 t0 = (p0 < NPTS) ? gOp[0][58 + j][p0] : make_float2(0.f, 0.f);
            float2 t1 = (p0 + 1 < NPTS) ? gOp[0][58 + j][p0 + 1] : make_float2(0.f, 0.f);
            Pa[j] = pk2(t0.x, t0.x);  Qa[j] = pk2(t0.y, t0.y);
            Pb[j] = pk2(t1.x, t1.x);  Qb[j] = pk2(t1.y, t1.y);
        }

        u64 y0p = 0ull, y1p = 0ull;
        if (p0 < NPTS) {
            F2U a; a.f = src[p0]; y0p = a.u;
            if (p0 + 1 < NPTS) { a.f = src[p0 + 1]; y1p = a.u; }
        }
        __syncthreads();
        for (int j = tid; j < YSLOTS; j += NTH) { YA[j] = 0ull; YB[j] = 0ull; }
        __syncthreads();
        YA[p0 + 6] = y0p;
        YA[p0 + 7] = y1p;
        __syncthreads();

        if (p0 < NPTS) {
            int row = n0 * NPTS + p0;
            out[row]        = lo2(y0p);
            out[half + row] = hi2(y0p);
            if (p0 + 1 < NPTS) {
                out[row + 1]        = lo2(y1p);
                out[half + row + 1] = hi2(y1p);
            }
        }

        const float4* RA = ((const float4*)YA) + tid;
        const float4* RB = ((const float4*)YB) + tid;
        float4* WA = ((float4*)YA) + (tid + 3);
        float4* WB = ((float4*)YB) + (tid + 3);

#define STEP(RSRC, WDST)                                                     \
    {                                                                        \
        u64 v[14];                                                           \
        _Pragma("unroll")                                                    \
        for (int j = 0; j < 7; j++) {                                        \
            float4 f = (RSRC)[j];                                            \
            v[2*j] = pk2(f.x, f.y); v[2*j + 1] = pk2(f.z, f.w);              \
        }                                                                    \
        u64 pa0 = mul2(Pa[0], v[0]);   u64 pa1 = mul2(Pa[1], v[1]);          \
        pa0 = fma2(Pa[2],  v[2],  pa0); pa1 = fma2(Pa[3],  v[3],  pa1);      \
        pa0 = fma2(Pa[4],  v[4],  pa0); pa1 = fma2(Pa[5],  v[5],  pa1);      \
        pa0 = fma2(Pa[6],  v[6],  pa0); pa1 = fma2(Pa[7],  v[7],  pa1);      \
        pa0 = fma2(Pa[8],  v[8],  pa0); pa1 = fma2(Pa[9],  v[9],  pa1);      \
        pa0 = fma2(Pa[10], v[10], pa0); pa1 = fma2(Pa[11], v[11], pa1);      \
        pa0 = fma2(Pa[12], v[12], pa0);                                      \
        u64 qa0 = mul2(Qa[0], v[0]);   u64 qa1 = mul2(Qa[1], v[1]);          \
        qa0 = fma2(Qa[2],  v[2],  qa0); qa1 = fma2(Qa[3],  v[3],  qa1);      \
        qa0 = fma2(Qa[4],  v[4],  qa0); qa1 = fma2(Qa[5],  v[5],  qa1);      \
        qa0 = fma2(Qa[6],  v[6],  qa0); qa1 = fma2(Qa[7],  v[7],  qa1);      \
        qa0 = fma2(Qa[8],  v[8],  qa0); qa1 = fma2(Qa[9],  v[9],  qa1);      \
        qa0 = fma2(Qa[10], v[10], qa0); qa1 = fma2(Qa[11], v[11], qa1);      \
        qa0 = fma2(Qa[12], v[12], qa0);                                      \
        u64 pb0 = mul2(Pb[0], v[1]);   u64 pb1 = mul2(Pb[1], v[2]);          \
        pb0 = fma2(Pb[2],  v[3],  pb0); pb1 = fma2(Pb[3],  v[4],  pb1);      \
        pb0 = fma2(Pb[4],  v[5],  pb0); pb1 = fma2(Pb[5],  v[6],  pb1);      \
        pb0 = fma2(Pb[6],  v[7],  pb0); pb1 = fma2(Pb[7],  v[8],  pb1);      \
        pb0 = fma2(Pb[8],  v[9],  pb0); pb1 = fma2(Pb[9],  v[10], pb1);      \
        pb0 = fma2(Pb[10], v[11], pb0); pb1 = fma2(Pb[11], v[12], pb1);      \
        pb0 = fma2(Pb[12], v[13], pb0);                                      \
        u64 qb0 = mul2(Qb[0], v[1]);   u64 qb1 = mul2(Qb[1], v[2]);          \
        qb0 = fma2(Qb[2],  v[3],  qb0); qb1 = fma2(Qb[3],  v[4],  qb1);      \
        qb0 = fma2(Qb[4],  v[5],  qb0); qb1 = fma2(Qb[5],  v[6],  qb1);      \
        qb0 = fma2(Qb[6],  v[7],  qb0); qb1 = fma2(Qb[7],  v[8],  qb1);      \
        qb0 = fma2(Qb[8],  v[9],  qb0); qb1 = fma2(Qb[9],  v[10], qb1);      \
        qb0 = fma2(Qb[10], v[11], qb0); qb1 = fma2(Qb[11], v[12], qb1);      \
        qb0 = fma2(Qb[12], v[13], qb0);                                      \
        u64 uP0 = add2(pa0, pa1);  u64 uQ0 = add2(qa0, qa1);                 \
        u64 uP1 = add2(pb0, pb1);  u64 uQ1 = add2(qb0, qb1);                 \
        F2U U0, V0, U1, V1; U0.u = uP0; V0.u = uQ0; U1.u = uP1; V1.u = uQ1;  \
        y0p = pk2(U0.f.x - V0.f.y, U0.f.y + V0.f.x);                         \
        y1p = pk2(U1.f.x - V1.f.y, U1.f.y + V1.f.x);                         \
        float4 sv; sv.x = lo2(y0p); sv.y = hi2(y0p);                         \
        sv.z = lo2(y1p); sv.w = hi2(y1p);                                    \
        *(WDST) = sv;                                                        \
        __syncthreads();                                                     \
    }

        int lastrow = (n0 + MITV < nitv) ? n0 + MITV : nitv;
        bool next_exists = (b + 1 < NCH) && (MITV * (b + 1) <= nitv);
        int top = next_exists ? (MITV * (b + 1) - 1) : lastrow;
        int napps = top - n0;

        int fl = 0;
        for (int a = 0; a < napps; a++) {
            if (!fl) { STEP(RA, WB) } else { STEP(RB, WA) }
            if (p0 < NPTS) {
                int row = (n0 + 1 + a) * NPTS + p0;
                out[row]        = lo2(y0p);
                out[half + row] = hi2(y0p);
                if (p0 + 1 < NPTS) {
                    out[row + 1]        = lo2(y1p);
                    out[half + row + 1] = hi2(y1p);
                }
            }
            fl ^= 1;
        }
#undef STEP
    }
}

extern "C" void kernel_launch(void* const* d_in, const int* in_sizes, int n_in,
                              void* d_out, int out_size)
{
    int p_idx = 1, t_idx = 0;
    if (n_in >= 2 && in_sizes[0] == 2 && in_sizes[1] != 2) { p_idx = 0; t_idx = 1; }
    const float* params = (const float*)d_in[p_idx];
    const int n_save = in_sizes[t_idx];

    cudaFuncSetAttribute(pe_all, cudaFuncAttributeMaxDynamicSharedMemorySize, SMEM_BYTES);
    pe_all<<<NBLK, NTH, SMEM_BYTES>>>(params, (float*)d_out, n_save);
}